// round 16
// baseline (speedup 1.0000x reference)
#include <cuda_runtime.h>
#include <cuda_bf16.h>
#include <mma.h>
#include <math.h>
#include <cstdint>

using namespace nvcuda;

#define NN 100000
#define EE 1600000
#define HID 128
#define HW  64          // uint32 (bf16x2) per feature row
#define NG 64
#define NC 10
#define SLOTS 96        // ELL slots per node; P(Poisson(16) > 96) ~ 1e-40

// ---- scratch (no allocs allowed; zero-initialized at load) ----
// activations as packed bf16x2 hi/lo pairs (ping-pong A/B)
__device__ uint32_t g_hAH[(size_t)NN * HW];
__device__ uint32_t g_hAL[(size_t)NN * HW];
__device__ uint32_t g_hBH[(size_t)NN * HW];
__device__ uint32_t g_hBL[(size_t)NN * HW];
__device__ uint32_t g_mH [(size_t)NN * HW];
__device__ uint32_t g_mL [(size_t)NN * HW];
// pre-split weights: 4 mats (W2l, W2r, W3l, W3r), each [128][64] uint32
__device__ uint32_t g_wH [4 * 128 * HW];
__device__ uint32_t g_wL [4 * 128 * HW];
__device__ float    g_pooled[NG * HID];
__device__ float    g_gcnt[NG];
__device__ int      g_cnt [NN];
__device__ int      g_ell [(size_t)NN * SLOTS];

// halfword0 = bf16(a), halfword1 = bf16(b)
__device__ __forceinline__ uint32_t pack_bf16x2(float a, float b) {
    uint32_t r;
    asm("cvt.rn.bf16x2.f32 %0, %1, %2;" : "=r"(r) : "f"(b), "f"(a));
    return r;
}
__device__ __forceinline__ void split4(float4 v, uint2& hi, uint2& lo) {
    uint32_t h01 = pack_bf16x2(v.x, v.y);
    uint32_t h23 = pack_bf16x2(v.z, v.w);
    float f0 = __uint_as_float(h01 << 16);
    float f1 = __uint_as_float(h01 & 0xFFFF0000u);
    float f2 = __uint_as_float(h23 << 16);
    float f3 = __uint_as_float(h23 & 0xFFFF0000u);
    hi = make_uint2(h01, h23);
    lo = make_uint2(pack_bf16x2(v.x - f0, v.y - f1), pack_bf16x2(v.z - f2, v.w - f3));
}
__device__ __forceinline__ void acc_bf2(float& a0, float& a1, uint32_t p) {
    a0 += __uint_as_float(p << 16);
    a1 += __uint_as_float(p & 0xFFFF0000u);
}

// =================== single-pass ELL build ===================
__global__ void ell_fill(const int* __restrict__ src, const int* __restrict__ dst,
                         int* __restrict__ cnt, int* __restrict__ ell, int E) {
    int e = blockIdx.x * blockDim.x + threadIdx.x;
    if (e >= E) return;
    int d = dst[e];
    int pos = atomicAdd(&cnt[d], 1);
    if (pos < SLOTS) ell[(size_t)d * SLOTS + pos] = src[e];
}

// =================== pre-split the 4 weight matrices ===================
__global__ void prep_w(const float* __restrict__ W2l, const float* __restrict__ W2r,
                       const float* __restrict__ W3l, const float* __restrict__ W3r,
                       uint32_t* __restrict__ wH, uint32_t* __restrict__ wL) {
    int idx = blockIdx.x * blockDim.x + threadIdx.x;     // 4*128*64
    if (idx >= 4 * 128 * HW) return;
    int m  = idx >> 13;           // matrix
    int k  = (idx >> 6) & 127;    // row
    int j2 = idx & 63;            // pair
    const float* W = (m == 0) ? W2l : (m == 1) ? W2r : (m == 2) ? W3l : W3r;
    float v0 = W[k * HID + 2 * j2];
    float v1 = W[k * HID + 2 * j2 + 1];
    uint32_t hi = pack_bf16x2(v0, v1);
    float f0 = __uint_as_float(hi << 16);
    float f1 = __uint_as_float(hi & 0xFFFF0000u);
    wH[idx] = hi;
    wL[idx] = pack_bf16x2(v0 - f0, v1 - f1);
}

// =================== layer 1 fused (warp per node); zeroes pooled/gcnt ===================
__global__ __launch_bounds__(256)
void l1_fused(const float* __restrict__ x, const int* __restrict__ cnt,
              const int* __restrict__ ell,
              const float* __restrict__ W1l, const float* __restrict__ W1r,
              const float* __restrict__ b1,
              uint32_t* __restrict__ hH, uint32_t* __restrict__ hL,
              float* __restrict__ pooled, float* __restrict__ gcnt, int N) {
    if (blockIdx.x == 0) {
        for (int i = threadIdx.x; i < NG * HID; i += 256) pooled[i] = 0.0f;
        if (threadIdx.x < NG) gcnt[threadIdx.x] = 0.0f;
    }
    int n = (blockIdx.x * blockDim.x + threadIdx.x) >> 5;
    int lane = threadIdx.x & 31;
    if (n >= N) return;
    int deg = min(cnt[n], SLOTS);
    const int* row = ell + (size_t)n * SLOTS;
    float s = 0.0f;
    for (int e = lane; e < deg; e += 32) s += x[row[e]];
#pragma unroll
    for (int o = 16; o; o >>= 1) s += __shfl_xor_sync(0xffffffffu, s, o);
    float mean = s / fmaxf((float)deg, 1.0f);
    float xn = x[n];
    float4 wl = *reinterpret_cast<const float4*>(W1l + lane * 4);
    float4 wr = *reinterpret_cast<const float4*>(W1r + lane * 4);
    float4 bb = *reinterpret_cast<const float4*>(b1 + lane * 4);
    float4 o;
    o.x = fmaxf(mean * wl.x + xn * wr.x + bb.x, 0.0f);
    o.y = fmaxf(mean * wl.y + xn * wr.y + bb.y, 0.0f);
    o.z = fmaxf(mean * wl.z + xn * wr.z + bb.z, 0.0f);
    o.w = fmaxf(mean * wl.w + xn * wr.w + bb.w, 0.0f);
    uint2 hi, lo;
    split4(o, hi, lo);
    *reinterpret_cast<uint2*>(hH + (size_t)n * HW + lane * 2) = hi;
    *reinterpret_cast<uint2*>(hL + (size_t)n * HW + lane * 2) = lo;
}

// =================== ELL gather mean from hi shadow; writes split mean ===================
__global__ __launch_bounds__(256)
void gather_mean(const uint32_t* __restrict__ hH, const int* __restrict__ cnt,
                 const int* __restrict__ ell,
                 uint32_t* __restrict__ mH, uint32_t* __restrict__ mL, int N) {
    int n = (blockIdx.x * blockDim.x + threadIdx.x) >> 5;
    int lane = threadIdx.x & 31;
    if (n >= N) return;
    int deg = min(cnt[n], SLOTS);
    const int* row = ell + (size_t)n * SLOTS;
    float a0 = 0.f, a1 = 0.f, a2 = 0.f, a3 = 0.f;
    float b0 = 0.f, b1 = 0.f, b2 = 0.f, b3 = 0.f;
    int e = 0;
    for (; e + 8 <= deg; e += 8) {
        int s0 = row[e + 0], s1 = row[e + 1], s2 = row[e + 2], s3 = row[e + 3];
        int s4 = row[e + 4], s5 = row[e + 5], s6 = row[e + 6], s7 = row[e + 7];
        uint2 v0 = *reinterpret_cast<const uint2*>(hH + (size_t)s0 * HW + lane * 2);
        uint2 v1 = *reinterpret_cast<const uint2*>(hH + (size_t)s1 * HW + lane * 2);
        uint2 v2 = *reinterpret_cast<const uint2*>(hH + (size_t)s2 * HW + lane * 2);
        uint2 v3 = *reinterpret_cast<const uint2*>(hH + (size_t)s3 * HW + lane * 2);
        uint2 v4 = *reinterpret_cast<const uint2*>(hH + (size_t)s4 * HW + lane * 2);
        uint2 v5 = *reinterpret_cast<const uint2*>(hH + (size_t)s5 * HW + lane * 2);
        uint2 v6 = *reinterpret_cast<const uint2*>(hH + (size_t)s6 * HW + lane * 2);
        uint2 v7 = *reinterpret_cast<const uint2*>(hH + (size_t)s7 * HW + lane * 2);
        acc_bf2(a0, a1, v0.x); acc_bf2(a2, a3, v0.y);
        acc_bf2(b0, b1, v1.x); acc_bf2(b2, b3, v1.y);
        acc_bf2(a0, a1, v2.x); acc_bf2(a2, a3, v2.y);
        acc_bf2(b0, b1, v3.x); acc_bf2(b2, b3, v3.y);
        acc_bf2(a0, a1, v4.x); acc_bf2(a2, a3, v4.y);
        acc_bf2(b0, b1, v5.x); acc_bf2(b2, b3, v5.y);
        acc_bf2(a0, a1, v6.x); acc_bf2(a2, a3, v6.y);
        acc_bf2(b0, b1, v7.x); acc_bf2(b2, b3, v7.y);
    }
    for (; e < deg; e++) {
        int s = row[e];
        uint2 v = *reinterpret_cast<const uint2*>(hH + (size_t)s * HW + lane * 2);
        acc_bf2(a0, a1, v.x); acc_bf2(a2, a3, v.y);
    }
    float ic = 1.0f / fmaxf((float)deg, 1.0f);
    float4 o;
    o.x = (a0 + b0) * ic;
    o.y = (a1 + b1) * ic;
    o.z = (a2 + b2) * ic;
    o.w = (a3 + b3) * ic;
    uint2 hi, lo;
    split4(o, hi, lo);
    *reinterpret_cast<uint2*>(mH + (size_t)n * HW + lane * 2) = hi;
    *reinterpret_cast<uint2*>(mL + (size_t)n * HW + lane * 2) = lo;
}

// =================== persistent wmma GEMM: pure-copy staging ===================
#define A_STRIDE 136
#define W_STRIDE 72
#define AH_OFF 0
#define AL_OFF 34816
#define WH_OFF 69632
#define WL_OFF 88064
#define GEMM_SMEM 106496
#define D_STRIDE 136

__global__ __launch_bounds__(256, 2)
void gemm_wmma(const uint32_t* __restrict__ selfH, const uint32_t* __restrict__ selfL,
               const uint32_t* __restrict__ mH, const uint32_t* __restrict__ mL,
               const uint32_t* __restrict__ wlH, const uint32_t* __restrict__ wlL,
               const uint32_t* __restrict__ wrH, const uint32_t* __restrict__ wrL,
               const float* __restrict__ bias,
               uint32_t* __restrict__ outH, uint32_t* __restrict__ outL,
               int N, int nTiles) {
    extern __shared__ char smem[];
    __nv_bfloat16* AH = reinterpret_cast<__nv_bfloat16*>(smem + AH_OFF);
    __nv_bfloat16* AL = reinterpret_cast<__nv_bfloat16*>(smem + AL_OFF);
    __nv_bfloat16* WH = reinterpret_cast<__nv_bfloat16*>(smem + WH_OFF);
    __nv_bfloat16* WL = reinterpret_cast<__nv_bfloat16*>(smem + WL_OFF);

    const int tid = threadIdx.x;
    const int wid = tid >> 5;
    const int wm  = wid >> 1;
    const int wn  = wid & 1;

    for (int tile = blockIdx.x; tile < nTiles; tile += gridDim.x) {
        const int n0 = tile * 128;

        wmma::fragment<wmma::accumulator, 16, 16, 16, float> accA[2][2], accB[2][2];
#pragma unroll
        for (int i = 0; i < 2; i++)
#pragma unroll
            for (int j = 0; j < 2; j++) {
                wmma::fill_fragment(accA[i][j], 0.0f);
                wmma::fill_fragment(accB[i][j], 0.0f);
            }

#pragma unroll
        for (int chunk = 0; chunk < 2; chunk++) {
            __syncthreads();   // prior phase's smem reads done

            // ---- stage A (pure uint4 copies: hi + lo) ----
            const uint32_t* srcH = (chunk == 0) ? mH : selfH;
            const uint32_t* srcL = (chunk == 0) ? mL : selfL;
            for (int idx = tid; idx < 4096; idx += 256) {
                int a = idx >> 11;           // 0: hi, 1: lo
                int r = (idx >> 4) & 127;
                int q = idx & 15;
                int n = n0 + r;
                uint4 v = make_uint4(0u, 0u, 0u, 0u);
                if (n < N) {
                    const uint32_t* s = (a ? srcL : srcH) + (size_t)n * HW;
                    v = *reinterpret_cast<const uint4*>(s + q * 4);
                }
                char* base = a ? (char*)AL : (char*)AH;
                *reinterpret_cast<uint4*>(base + r * 272 + q * 16) = v;
            }

            const uint32_t* wHsrc = (chunk == 0) ? wlH : wrH;
            const uint32_t* wLsrc = (chunk == 0) ? wlL : wrL;
#pragma unroll
            for (int jh = 0; jh < 2; jh++) {
                if (jh == 1) __syncthreads();
                // ---- stage W half (pure uint4 copies) ----
                for (int idx = tid; idx < 2048; idx += 256) {
                    int a = idx >> 10;
                    int k = (idx >> 3) & 127;
                    int q = idx & 7;
                    const uint32_t* s = (a ? wLsrc : wHsrc) + k * HW + jh * 32;
                    uint4 v = *reinterpret_cast<const uint4*>(s + q * 4);
                    char* base = a ? (char*)WL : (char*)WH;
                    *reinterpret_cast<uint4*>(base + k * 144 + q * 16) = v;
                }
                __syncthreads();

                wmma::fragment<wmma::accumulator, 16, 16, 16, float> (*acc)[2] =
                    (jh == 0) ? accA : accB;
#pragma unroll
                for (int k0 = 0; k0 < 128; k0 += 16) {
                    wmma::fragment<wmma::matrix_a, 16, 16, 16, __nv_bfloat16, wmma::row_major> a0h, a1h, a0l, a1l;
                    wmma::fragment<wmma::matrix_b, 16, 16, 16, __nv_bfloat16, wmma::row_major> b0h, b1h, b0l, b1l;
                    wmma::load_matrix_sync(a0h, AH + (wm * 32 +  0) * A_STRIDE + k0, A_STRIDE);
                    wmma::load_matrix_sync(a1h, AH + (wm * 32 + 16) * A_STRIDE + k0, A_STRIDE);
                    wmma::load_matrix_sync(b0h, WH + k0 * W_STRIDE + wn * 32 +  0, W_STRIDE);
                    wmma::load_matrix_sync(b1h, WH + k0 * W_STRIDE + wn * 32 + 16, W_STRIDE);
                    wmma::mma_sync(acc[0][0], a0h, b0h, acc[0][0]);
                    wmma::mma_sync(acc[0][1], a0h, b1h, acc[0][1]);
                    wmma::mma_sync(acc[1][0], a1h, b0h, acc[1][0]);
                    wmma::mma_sync(acc[1][1], a1h, b1h, acc[1][1]);
                    wmma::load_matrix_sync(b0l, WL + k0 * W_STRIDE + wn * 32 +  0, W_STRIDE);
                    wmma::load_matrix_sync(b1l, WL + k0 * W_STRIDE + wn * 32 + 16, W_STRIDE);
                    wmma::mma_sync(acc[0][0], a0h, b0l, acc[0][0]);
                    wmma::mma_sync(acc[0][1], a0h, b1l, acc[0][1]);
                    wmma::mma_sync(acc[1][0], a1h, b0l, acc[1][0]);
                    wmma::mma_sync(acc[1][1], a1h, b1l, acc[1][1]);
                    wmma::load_matrix_sync(a0l, AL + (wm * 32 +  0) * A_STRIDE + k0, A_STRIDE);
                    wmma::load_matrix_sync(a1l, AL + (wm * 32 + 16) * A_STRIDE + k0, A_STRIDE);
                    wmma::mma_sync(acc[0][0], a0l, b0h, acc[0][0]);
                    wmma::mma_sync(acc[0][1], a0l, b1h, acc[0][1]);
                    wmma::mma_sync(acc[1][0], a1l, b0h, acc[1][0]);
                    wmma::mma_sync(acc[1][1], a1l, b1h, acc[1][1]);
                }
            }
        }

        // ---- epilogue: Ds overlay -> bias+relu -> split -> packed stores ----
        __syncthreads();
        float* Ds = reinterpret_cast<float*>(smem);   // [128][D_STRIDE]
#pragma unroll
        for (int i = 0; i < 2; i++)
#pragma unroll
            for (int j = 0; j < 2; j++) {
                wmma::store_matrix_sync(Ds + (wm * 32 + i * 16) * D_STRIDE + wn * 32 + j * 16,
                                        accA[i][j], D_STRIDE, wmma::mem_row_major);
                wmma::store_matrix_sync(Ds + (wm * 32 + i * 16) * D_STRIDE + 64 + wn * 32 + j * 16,
                                        accB[i][j], D_STRIDE, wmma::mem_row_major);
            }
        __syncthreads();

        for (int idx = tid; idx < 128 * 32; idx += 256) {
            int r  = idx >> 5;
            int jq = (idx & 31) * 4;
            int n  = n0 + r;
            if (n < N) {
                float4 d  = *reinterpret_cast<const float4*>(Ds + r * D_STRIDE + jq);
                float4 bb = *reinterpret_cast<const float4*>(bias + jq);
                float4 o;
                o.x = fmaxf(d.x + bb.x, 0.0f);
                o.y = fmaxf(d.y + bb.y, 0.0f);
                o.z = fmaxf(d.z + bb.z, 0.0f);
                o.w = fmaxf(d.w + bb.w, 0.0f);
                uint2 hi, lo;
                split4(o, hi, lo);
                *reinterpret_cast<uint2*>(outH + (size_t)n * HW + jq / 2) = hi;
                *reinterpret_cast<uint2*>(outL + (size_t)n * HW + jq / 2) = lo;
            }
        }
    }
}

// =================== pool (reads hi+lo pair) + classifier ===================
__global__ void pool_kernel(const uint32_t* __restrict__ hH, const uint32_t* __restrict__ hL,
                            const int* __restrict__ batch,
                            float* pooled, float* gcnt, int N) {
    const int f = threadIdx.x;
    const int w = f >> 1;
    const bool top = f & 1;
    int start = blockIdx.x * 512;
    if (start >= N) return;
    int end = min(start + 512, N);
    float acc = 0.0f, run = 0.0f;
    int gprev = batch[start];
    for (int n = start; n < end; n++) {
        int g = batch[n];
        if (g != gprev) {
            atomicAdd(&pooled[gprev * HID + f], acc);
            if (f == 0) atomicAdd(&gcnt[gprev], run);
            acc = 0.0f; run = 0.0f; gprev = g;
        }
        uint32_t a = hH[(size_t)n * HW + w];
        uint32_t b = hL[(size_t)n * HW + w];
        float v = top ? (__uint_as_float(a & 0xFFFF0000u) + __uint_as_float(b & 0xFFFF0000u))
                      : (__uint_as_float(a << 16) + __uint_as_float(b << 16));
        acc += v;
        run += 1.0f;
    }
    atomicAdd(&pooled[gprev * HID + f], acc);
    if (f == 0) atomicAdd(&gcnt[gprev], run);
}

__global__ void final_kernel(const float* __restrict__ pooled, const float* __restrict__ gcnt,
                             const float* __restrict__ Wfc, const float* __restrict__ bfc,
                             float* __restrict__ out) {
    __shared__ float sl[NG * NC];
    int t = threadIdx.x;
    if (t < NG * NC) {
        int g = t / NC, c = t % NC;
        float inv = 1.0f / fmaxf(gcnt[g], 1.0f);
        float s = bfc[c];
#pragma unroll 8
        for (int k = 0; k < HID; k++)
            s += pooled[g * HID + k] * inv * Wfc[k * NC + c];
        sl[t] = s;
    }
    __syncthreads();
    if (t < NG * NC) {
        int g = t / NC;
        float m = -1e30f;
        for (int c2 = 0; c2 < NC; c2++) m = fmaxf(m, sl[g * NC + c2]);
        float sum = 0.0f;
        for (int c2 = 0; c2 < NC; c2++) sum += __expf(sl[g * NC + c2] - m);
        out[t] = sl[t] - m - logf(sum);
    }
}

extern "C" void kernel_launch(void* const* d_in, const int* in_sizes, int n_in,
                              void* d_out, int out_size) {
    const float* x    = (const float*)d_in[0];
    const int*   ei   = (const int*)  d_in[1];
    const int*   batch= (const int*)  d_in[2];
    const float* W1l  = (const float*)d_in[3];
    const float* W1r  = (const float*)d_in[4];
    const float* b1   = (const float*)d_in[5];
    const float* W2l  = (const float*)d_in[6];
    const float* W2r  = (const float*)d_in[7];
    const float* b2   = (const float*)d_in[8];
    const float* W3l  = (const float*)d_in[9];
    const float* W3r  = (const float*)d_in[10];
    const float* b3   = (const float*)d_in[11];
    const float* Wfc  = (const float*)d_in[12];
    const float* bfc  = (const float*)d_in[13];
    float* out = (float*)d_out;

    const int N = in_sizes[0];
    const int E = in_sizes[1] / 2;
    const int* src = ei;
    const int* dst = ei + E;

    uint32_t *hAH, *hAL, *hBH, *hBL, *mH, *mL, *wH, *wL;
    float *pooled, *gcnt;
    int *cnt, *ell;
    cudaGetSymbolAddress((void**)&hAH,    g_hAH);
    cudaGetSymbolAddress((void**)&hAL,    g_hAL);
    cudaGetSymbolAddress((void**)&hBH,    g_hBH);
    cudaGetSymbolAddress((void**)&hBL,    g_hBL);
    cudaGetSymbolAddress((void**)&mH,     g_mH);
    cudaGetSymbolAddress((void**)&mL,     g_mL);
    cudaGetSymbolAddress((void**)&wH,     g_wH);
    cudaGetSymbolAddress((void**)&wL,     g_wL);
    cudaGetSymbolAddress((void**)&pooled, g_pooled);
    cudaGetSymbolAddress((void**)&gcnt,   g_gcnt);
    cudaGetSymbolAddress((void**)&cnt,    g_cnt);
    cudaGetSymbolAddress((void**)&ell,    g_ell);

    cudaFuncSetAttribute(gemm_wmma, cudaFuncAttributeMaxDynamicSharedMemorySize, GEMM_SMEM);

    // ---- graph prep: ELL build + weight pre-split ----
    cudaMemsetAsync(cnt, 0, (size_t)N * sizeof(int));
    ell_fill<<<(E + 255) / 256, 256>>>(src, dst, cnt, ell, E);
    prep_w<<<(4 * 128 * HW + 255) / 256, 256>>>(W2l, W2r, W3l, W3r, wH, wL);

    // ---- layer 1 (fused; writes split pair; zeroes pooled/gcnt) ----
    const int gwarps_grid = (N * 32 + 255) / 256;    // 12500
    l1_fused<<<gwarps_grid, 256>>>(x, cnt, ell, W1l, W1r, b1, hAH, hAL,
                                   pooled, gcnt, N);

    const int nTiles = (N + 127) / 128;              // 782
    const int gemmGrid = nTiles < 296 ? nTiles : 296;
    const int MOFF = 128 * HW;                        // per-matrix offset in wH/wL

    // ---- layer 2 ----
    gather_mean<<<gwarps_grid, 256>>>(hAH, cnt, ell, mH, mL, N);
    gemm_wmma<<<gemmGrid, 256, GEMM_SMEM>>>(hAH, hAL, mH, mL,
                                            wH + 0 * MOFF, wL + 0 * MOFF,
                                            wH + 1 * MOFF, wL + 1 * MOFF,
                                            b2, hBH, hBL, N, nTiles);

    // ---- layer 3 ----
    gather_mean<<<gwarps_grid, 256>>>(hBH, cnt, ell, mH, mL, N);
    gemm_wmma<<<gemmGrid, 256, GEMM_SMEM>>>(hBH, hBL, mH, mL,
                                            wH + 2 * MOFF, wL + 2 * MOFF,
                                            wH + 3 * MOFF, wL + 3 * MOFF,
                                            b3, hAH, hAL, N, nTiles);

    // ---- pool + classifier ----
    pool_kernel<<<(N + 511) / 512, 128>>>(hAH, hAL, batch, pooled, gcnt, N);
    final_kernel<<<1, NG * NC>>>(pooled, gcnt, Wfc, bfc, out);
}